// round 15
// baseline (speedup 1.0000x reference)
#include <cuda_runtime.h>
#include <math.h>

// ---------------------------------------------------------------------------
// ModelSpectral: hierarchical GraphSAGE + MLP + n x 2 Householder QR
// R12: R11 conv untouched (893us baseline). Packed int2 colidx (halves the
//      CSR fill's scattered-write sectors) + MLP k-major float4 weight loads
//      (LDS.128, 4x fewer shared-mem instructions).
// ---------------------------------------------------------------------------

#define NL0 524288
#define NL1 65536
#define NL2 8192
#define NL3 1024
#define NL4 128
#define NL5 16

#define NOFF0 0
#define NOFF1 524288
#define NOFF2 589824
#define NOFF3 598016
#define NOFF4 599040
#define NOFF5 599168
#define NTOT  599184

#define EL0 8388608
#define EL1 1048576
#define EL2 131072
#define EL3 16384
#define EL4 2048
#define EL5 256

#define EOFF0 0
#define EOFF1 8388608
#define EOFF2 9437184
#define EOFF3 9568256
#define EOFF4 9584640
#define EOFF5 9586688
#define ETOT  9586944

// scratch (device globals; no allocations allowed)
__device__ float  g_bufA[NL0 * 32];   // fp32 activations (conv1 in / conv2 out)
__device__ float  g_bufB[NL0 * 32];   // fp32 activations (conv1 out / conv2 in)
__device__ int    g_rowptr[NTOT + 1];
__device__ int2   g_colpair[ETOT];    // .x = raw src (conv2), .y = inv[src] (conv1)
__device__ int    g_cnt[NTOT];
__device__ int    g_partials[1024];
__device__ float  g_mat[NL0 * 2];
__device__ double g_red[3];
__device__ double g_scal[6];

// fast accurate-enough tanh: 1x EX2 + 1x fast div (~1e-7 abs err)
__device__ __forceinline__ float ftanh(float v) {
    float x = fminf(fmaxf(v, -15.f), 15.f);
    float e;
    asm("ex2.approx.f32 %0, %1;" : "=f"(e) : "f"(x * 2.8853900817779268f));
    return __fdividef(e - 1.f, e + 1.f);
}

// ---------------------------------------------------------------------------
// init: clear g_cnt everywhere; block 0 also computes the coarsest level
// (x = eye(2), coarse_edges = [[0,1],[1,0]] constant) and zeroes QR sums.
// ---------------------------------------------------------------------------
__global__ void init_kernel(const float* __restrict__ Wcl,
                            const float* __restrict__ Wcr,
                            const float* __restrict__ bc) {
    int i = blockIdx.x * blockDim.x + threadIdx.x;
    if (i < NTOT) g_cnt[i] = 0;
    if (blockIdx.x == 0) {
        int t = threadIdx.x;
        if (t < 64) {
            int r = t >> 5, c = t & 31;
            g_bufA[t] = ftanh(Wcl[(1 - r) * 32 + c] + Wcr[r * 32 + c] + bc[c]);
        }
        if (t < 3) g_red[t] = 0.0;
    }
}

// ---------------------------------------------------------------------------
// CSR build (by destination), ALL levels concatenated
// ---------------------------------------------------------------------------
__global__ void count_all_kernel(const int* __restrict__ e0, const int* __restrict__ e1,
                                 const int* __restrict__ e2, const int* __restrict__ e3,
                                 const int* __restrict__ e4, const int* __restrict__ e5) {
    int t = blockIdx.x * blockDim.x + threadIdx.x;
    int d;
    if      (t < EOFF1) d = NOFF0 + e0[EL0 + t];
    else if (t < EOFF2) d = NOFF1 + e1[EL1 + (t - EOFF1)];
    else if (t < EOFF3) d = NOFF2 + e2[EL2 + (t - EOFF2)];
    else if (t < EOFF4) d = NOFF3 + e3[EL3 + (t - EOFF3)];
    else if (t < EOFF5) d = NOFF4 + e4[EL4 + (t - EOFF4)];
    else if (t < ETOT)  d = NOFF5 + e5[EL5 + (t - EOFF5)];
    else return;
    atomicAdd(&g_cnt[d], 1);
}

// block-local exclusive scan (1024 items / block), block sums -> g_partials
__global__ void scan1_kernel() {
    __shared__ int sm[256];
    int t = threadIdx.x;
    int base = blockIdx.x * 1024 + t * 4;
    int v[4];
#pragma unroll
    for (int i = 0; i < 4; i++) v[i] = (base + i < NTOT) ? g_cnt[base + i] : 0;
    int s = v[0] + v[1] + v[2] + v[3];
    sm[t] = s;
    __syncthreads();
    for (int off = 1; off < 256; off <<= 1) {
        int y = (t >= off) ? sm[t - off] : 0;
        __syncthreads();
        sm[t] += y;
        __syncthreads();
    }
    int incl = sm[t];
    if (t == 255) g_partials[blockIdx.x] = incl;
    int run = incl - s;
#pragma unroll
    for (int i = 0; i < 4; i++) {
        if (base + i < NTOT) g_rowptr[base + i] = run;
        run += v[i];
    }
}

// exclusive scan of block partials (nb <= 1024), single block
__global__ void scan2_kernel(int nb) {
    __shared__ int sm[1024];
    int t = threadIdx.x;
    int v = (t < nb) ? g_partials[t] : 0;
    sm[t] = v;
    __syncthreads();
    for (int off = 1; off < 1024; off <<= 1) {
        int y = (t >= off) ? sm[t - off] : 0;
        __syncthreads();
        sm[t] += y;
        __syncthreads();
    }
    if (t < nb) g_partials[t] = sm[t] - v;
}

// add partials, clear cnt for the fill cursor, seal rowptr
__global__ void scan3_kernel() {
    int i = blockIdx.x * blockDim.x + threadIdx.x;
    if (i < NTOT) {
        g_rowptr[i] += g_partials[i >> 10];
        g_cnt[i] = 0;
    }
    if (i == 0) g_rowptr[NTOT] = ETOT;
}

// fill: one packed int2 write per edge (raw src + inv-mapped src)
__global__ void fill_all_kernel(const int* __restrict__ e0, const int* __restrict__ e1,
                                const int* __restrict__ e2, const int* __restrict__ e3,
                                const int* __restrict__ e4, const int* __restrict__ e5,
                                const int* __restrict__ i0, const int* __restrict__ i1,
                                const int* __restrict__ i2, const int* __restrict__ i3,
                                const int* __restrict__ i4, const int* __restrict__ i5) {
    int t = blockIdx.x * blockDim.x + threadIdx.x;
    int s, d, m;
    if      (t < EOFF1) { s = e0[t];         d = NOFF0 + e0[EL0 + t]; m = __ldg(&i0[s]); }
    else if (t < EOFF2) { int u = t - EOFF1; s = e1[u]; d = NOFF1 + e1[EL1 + u]; m = __ldg(&i1[s]); }
    else if (t < EOFF3) { int u = t - EOFF2; s = e2[u]; d = NOFF2 + e2[EL2 + u]; m = __ldg(&i2[s]); }
    else if (t < EOFF4) { int u = t - EOFF3; s = e3[u]; d = NOFF3 + e3[EL3 + u]; m = __ldg(&i3[s]); }
    else if (t < EOFF5) { int u = t - EOFF4; s = e4[u]; d = NOFF4 + e4[EL4 + u]; m = __ldg(&i4[s]); }
    else if (t < ETOT)  { int u = t - EOFF5; s = e5[u]; d = NOFF5 + e5[EL5 + u]; m = __ldg(&i5[s]); }
    else return;
    int p = g_rowptr[d] + atomicAdd(&g_cnt[d], 1);
    g_colpair[p] = make_int2(s, m);
}

// ---------------------------------------------------------------------------
// fused SAGEConv: y = tanh(mean_agg(x) @ Wl + x @ Wr + b)
// QUARTER-warp node assignment (4 chains/warp); lane = feature quad
// (float4, one warp LDG.128 = 4 neighbor rows). Neighbor indices hoisted
// 16-ahead. MAPPED selects the .y (inv-mapped) component of the pair.
// ---------------------------------------------------------------------------
template <int XSEL, int MAPPED, int SELF_INDIRECT, int STREAM_OUT>
__global__ __launch_bounds__(128, 4)
void sage_conv_kernel(const int* __restrict__ inv,
                      int n, int noff,
                      const float* __restrict__ Wl,
                      const float* __restrict__ Wr,
                      const float* __restrict__ b) {
    const float* __restrict__ x = XSEL ? g_bufB : g_bufA;
    float*       __restrict__ y = XSEL ? g_bufA : g_bufB;

    int lane = threadIdx.x & 31;
    int qtr  = lane >> 3;          // which node of the 4 (0..3)
    int sp   = lane & 7;           // feature-quad index (features 4sp..4sp+3)
    int wloc = threadIdx.x >> 5;   // 4 warps per block
    int gwarp   = (blockIdx.x * blockDim.x + threadIdx.x) >> 5;
    int totwarp = (gridDim.x * blockDim.x) >> 5;

    float wl[32], wr[32];
#pragma unroll
    for (int k = 0; k < 32; k++) {
        wl[k] = Wl[k * 32 + lane];
        wr[k] = Wr[k * 32 + lane];
    }
    float bj = b[lane];

    __shared__ float sm[4][4][64];   // [warp][node][agg32|self32]

    for (int base = gwarp * 4; base < n; base += totwarp * 4) {
        int node = base + qtr;
        bool valid = node < n;

        int r0 = 0, r1 = 0;
        if (valid) {
            r0 = __ldg(&g_rowptr[noff + node]);
            r1 = __ldg(&g_rowptr[noff + node + 1]);
        }
        int deg = r1 - r0;

        float ax = 0.f, ay = 0.f, az = 0.f, aw = 0.f;
        for (int bs = r0; bs < r1; bs += 16) {
            // hoist 16 neighbor indices (covers the avg-16 degree in one shot)
            int c[16];
#pragma unroll
            for (int i = 0; i < 16; i++) {
                int idx = bs + i;
                if (idx < r1) {
                    int2 cp = __ldcs(&g_colpair[idx]);
                    c[i] = MAPPED ? cp.y : cp.x;
                } else {
                    c[i] = -1;
                }
            }
#pragma unroll
            for (int ph = 0; ph < 2; ph++) {
                float4 f[8];
#pragma unroll
                for (int i = 0; i < 8; i++) {
                    int cc = c[ph * 8 + i];
                    if (cc >= 0)
                        f[i] = __ldg((const float4*)(x + (cc << 5) + 4 * sp));
                    else
                        f[i] = make_float4(0.f, 0.f, 0.f, 0.f);
                }
                // tree sum of 8 float4s
#pragma unroll
                for (int st = 4; st >= 1; st >>= 1) {
#pragma unroll
                    for (int i = 0; i < st; i++) {
                        f[i].x += f[i + st].x;
                        f[i].y += f[i + st].y;
                        f[i].z += f[i + st].z;
                        f[i].w += f[i + st].w;
                    }
                }
                ax += f[0].x; ay += f[0].y; az += f[0].z; aw += f[0].w;
            }
        }
        float s = 1.0f / (float)(deg > 0 ? deg : 1);
        ax *= s; ay *= s; az *= s; aw *= s;

        float4 sf = make_float4(0.f, 0.f, 0.f, 0.f);
        if (valid) {
            int selfrow = SELF_INDIRECT ? __ldg(&inv[node]) : node;
            sf = __ldg((const float4*)(x + (selfrow << 5) + 4 * sp));
        }

        *((float4*)&sm[wloc][qtr][4 * sp])      = make_float4(ax, ay, az, aw);
        *((float4*)&sm[wloc][qtr][32 + 4 * sp]) = sf;
        __syncwarp();

#pragma unroll
        for (int h = 0; h < 4; h++) {
            int onode = base + h;
            if (onode < n) {
                float acc = bj;
                const float4* s4 = (const float4*)sm[wloc][h];
#pragma unroll
                for (int q = 0; q < 8; q++) {
                    float4 va = s4[q];          // agg[4q..4q+3]
                    acc = fmaf(va.x, wl[4 * q + 0], acc);
                    acc = fmaf(va.y, wl[4 * q + 1], acc);
                    acc = fmaf(va.z, wl[4 * q + 2], acc);
                    acc = fmaf(va.w, wl[4 * q + 3], acc);
                    float4 vs = s4[8 + q];      // self[4q..4q+3]
                    acc = fmaf(vs.x, wr[4 * q + 0], acc);
                    acc = fmaf(vs.y, wr[4 * q + 1], acc);
                    acc = fmaf(vs.z, wr[4 * q + 2], acc);
                    acc = fmaf(vs.w, wr[4 * q + 3], acc);
                }
                float r = ftanh(acc);
                if (STREAM_OUT) __stcs(&y[(onode << 5) + lane], r);
                else            y[(onode << 5) + lane] = r;
            }
        }
        __syncwarp();
    }
}

// ---------------------------------------------------------------------------
// MLP tail: 32 -> 16 -> 32 -> 32 -> 2 (tanh on first three), reads bufA
// (streaming), writes g_mat and accumulates the QR Gram sums.
// k-major loops with float4 weight loads (LDS.128: 4 weights/instruction).
// ---------------------------------------------------------------------------
__global__ void mlp_kernel(int n,
                           const float* __restrict__ W1, const float* __restrict__ b1,
                           const float* __restrict__ W2, const float* __restrict__ b2,
                           const float* __restrict__ W3, const float* __restrict__ b3,
                           const float* __restrict__ Wf, const float* __restrict__ bf) {
    __shared__ __align__(16) float sW1[512], sW2[512], sW3[1024], sWf[64];
    __shared__ float sb1[16], sb2[32], sb3[32], sbf[2];
    __shared__ double smr[3][8];
    int t = threadIdx.x;
    for (int i = t; i < 512; i += blockDim.x)  sW1[i] = W1[i];
    for (int i = t; i < 512; i += blockDim.x)  sW2[i] = W2[i];
    for (int i = t; i < 1024; i += blockDim.x) sW3[i] = W3[i];
    for (int i = t; i < 64; i += blockDim.x)   sWf[i] = Wf[i];
    if (t < 16) sb1[t] = b1[t];
    if (t < 32) sb2[t] = b2[t];
    if (t < 32) sb3[t] = b3[t];
    if (t < 2)  sbf[t] = bf[t];
    __syncthreads();

    const float4* sW1v = (const float4*)sW1;   // [32][4]  (16 outs / 4)
    const float4* sW2v = (const float4*)sW2;   // [16][8]
    const float4* sW3v = (const float4*)sW3;   // [32][8]
    const float2* sWfv = (const float2*)sWf;   // [32]

    double s11 = 0.0, s12 = 0.0, s22 = 0.0;

    for (int i = blockIdx.x * blockDim.x + t; i < n;
         i += gridDim.x * blockDim.x) {
        float h[32];
        const float4* xr = (const float4*)(g_bufA + i * 32);
#pragma unroll
        for (int q = 0; q < 8; q++) {
            float4 v = __ldcs(&xr[q]);
            h[q * 4] = v.x; h[q * 4 + 1] = v.y;
            h[q * 4 + 2] = v.z; h[q * 4 + 3] = v.w;
        }

        // layer 1: 32 -> 16 (k-major, float4 weights)
        float a1[16];
#pragma unroll
        for (int j = 0; j < 16; j++) a1[j] = sb1[j];
#pragma unroll
        for (int k = 0; k < 32; k++) {
            float hk = h[k];
#pragma unroll
            for (int j4 = 0; j4 < 4; j4++) {
                float4 w = sW1v[k * 4 + j4];
                a1[j4 * 4 + 0] = fmaf(hk, w.x, a1[j4 * 4 + 0]);
                a1[j4 * 4 + 1] = fmaf(hk, w.y, a1[j4 * 4 + 1]);
                a1[j4 * 4 + 2] = fmaf(hk, w.z, a1[j4 * 4 + 2]);
                a1[j4 * 4 + 3] = fmaf(hk, w.w, a1[j4 * 4 + 3]);
            }
        }
        float t1[16];
#pragma unroll
        for (int j = 0; j < 16; j++) t1[j] = ftanh(a1[j]);

        // layer 2: 16 -> 32
        float a2[32];
#pragma unroll
        for (int j = 0; j < 32; j++) a2[j] = sb2[j];
#pragma unroll
        for (int k = 0; k < 16; k++) {
            float hk = t1[k];
#pragma unroll
            for (int j4 = 0; j4 < 8; j4++) {
                float4 w = sW2v[k * 8 + j4];
                a2[j4 * 4 + 0] = fmaf(hk, w.x, a2[j4 * 4 + 0]);
                a2[j4 * 4 + 1] = fmaf(hk, w.y, a2[j4 * 4 + 1]);
                a2[j4 * 4 + 2] = fmaf(hk, w.z, a2[j4 * 4 + 2]);
                a2[j4 * 4 + 3] = fmaf(hk, w.w, a2[j4 * 4 + 3]);
            }
        }
        float t2[32];
#pragma unroll
        for (int j = 0; j < 32; j++) t2[j] = ftanh(a2[j]);

        // layer 3: 32 -> 32
        float a3[32];
#pragma unroll
        for (int j = 0; j < 32; j++) a3[j] = sb3[j];
#pragma unroll
        for (int k = 0; k < 32; k++) {
            float hk = t2[k];
#pragma unroll
            for (int j4 = 0; j4 < 8; j4++) {
                float4 w = sW3v[k * 8 + j4];
                a3[j4 * 4 + 0] = fmaf(hk, w.x, a3[j4 * 4 + 0]);
                a3[j4 * 4 + 1] = fmaf(hk, w.y, a3[j4 * 4 + 1]);
                a3[j4 * 4 + 2] = fmaf(hk, w.z, a3[j4 * 4 + 2]);
                a3[j4 * 4 + 3] = fmaf(hk, w.w, a3[j4 * 4 + 3]);
            }
        }

        // final: 32 -> 2 (float2 weights)
        float o0 = sbf[0], o1 = sbf[1];
#pragma unroll
        for (int k = 0; k < 32; k++) {
            float hk = ftanh(a3[k]);
            float2 w = sWfv[k];
            o0 = fmaf(hk, w.x, o0);
            o1 = fmaf(hk, w.y, o1);
        }

        g_mat[i * 2]     = o0;
        g_mat[i * 2 + 1] = o1;
        s11 += (double)o0 * o0;
        s12 += (double)o0 * o1;
        s22 += (double)o1 * o1;
    }

    // block reduction of Gram sums
#pragma unroll
    for (int off = 16; off; off >>= 1) {
        s11 += __shfl_down_sync(0xffffffffu, s11, off);
        s12 += __shfl_down_sync(0xffffffffu, s12, off);
        s22 += __shfl_down_sync(0xffffffffu, s22, off);
    }
    int lane = t & 31, w = t >> 5;
    if (lane == 0) { smr[0][w] = s11; smr[1][w] = s12; smr[2][w] = s22; }
    __syncthreads();
    if (t == 0) {
        double a = 0, bb = 0, c = 0;
        int nw = blockDim.x >> 5;
        for (int i = 0; i < nw; i++) { a += smr[0][i]; bb += smr[1][i]; c += smr[2][i]; }
        atomicAdd(&g_red[0], a);
        atomicAdd(&g_red[1], bb);
        atomicAdd(&g_red[2], c);
    }
}

// ---------------------------------------------------------------------------
// QR (n x 2) via LAPACK-convention Householder reflections
// ---------------------------------------------------------------------------
__global__ void qr_scalars_kernel() {
    double s11 = g_red[0], s12 = g_red[1], s22 = g_red[2];
    double a10 = g_mat[0], a20 = g_mat[1];
    double a11 = g_mat[2], a21 = g_mat[3];
    double nrm1   = sqrt(s11);
    double beta1  = -copysign(nrm1, a10);
    double denom1 = a10 - beta1;
    double tau1   = (beta1 - a10) / beta1;
    double gg     = a20 + (s12 - a10 * a20) / denom1;   // v1^T a2
    double c20    = a20 - tau1 * gg;                    // (H1 a2)[0] = r12
    double v11    = a11 / denom1;
    double c21    = a21 - tau1 * v11 * gg;              // (H1 a2)[1]
    double n2sq   = s22 - c20 * c20;
    if (n2sq < 0) n2sq = 0;
    double nrm2   = sqrt(n2sq);
    double beta2  = -copysign(nrm2, c21);
    double denom2 = c21 - beta2;
    double tau2   = (beta2 - c21) / beta2;
    double v1v2 = v11 + (-gg - c20 - v11 * c21) / denom2;
    double w    = v11 - tau2 * v1v2;
    g_scal[0] = tau1;  g_scal[1] = 1.0 / denom1; g_scal[2] = gg;
    g_scal[3] = tau2;  g_scal[4] = 1.0 / denom2; g_scal[5] = w;
}

__global__ void qr_finalize_kernel(float* __restrict__ out, int n) {
    float tau1 = (float)g_scal[0], id1 = (float)g_scal[1], gg = (float)g_scal[2];
    float tau2 = (float)g_scal[3], id2 = (float)g_scal[4], w  = (float)g_scal[5];
    for (int j = blockIdx.x * blockDim.x + threadIdx.x; j < n;
         j += gridDim.x * blockDim.x) {
        float a1j = g_mat[2 * j], a2j = g_mat[2 * j + 1];
        float v1 = (j == 0) ? 1.f : a1j * id1;
        float c2 = a2j - tau1 * v1 * gg;
        float v2 = (j == 0) ? 0.f : ((j == 1) ? 1.f : c2 * id2);
        float q0 = -tau1 * v1;
        if (j == 0) q0 += 1.f;
        float q1 = -tau2 * v2 - tau1 * v1 * w;
        if (j == 1) q1 += 1.f;
        out[2 * j]     = q0;
        out[2 * j + 1] = q1;
    }
}

// ---------------------------------------------------------------------------
static inline int imin(int a, int b) { return a < b ? a : b; }
static inline int imax(int a, int b) { return a > b ? a : b; }

extern "C" void kernel_launch(void* const* d_in, const int* in_sizes, int n_in,
                              void* d_out, int out_size) {
    (void)in_sizes; (void)n_in; (void)out_size;
    static const int LS[6]   = {NL0, NL1, NL2, NL3, NL4, NL5};
    static const int NOFF[6] = {NOFF0, NOFF1, NOFF2, NOFF3, NOFF4, NOFF5};

    const int* edges[6];
    const int* inv[6];
    for (int l = 0; l < 6; l++) {
        edges[l] = (const int*)d_in[2 * l];
        inv[l]   = (const int*)d_in[2 * l + 1];
    }
    const float* Wcl = (const float*)d_in[13];
    const float* Wcr = (const float*)d_in[14];
    const float* bc  = (const float*)d_in[15];
    const float* Wp_l[2] = {(const float*)d_in[16], (const float*)d_in[19]};
    const float* Wp_r[2] = {(const float*)d_in[17], (const float*)d_in[20]};
    const float* bp[2]   = {(const float*)d_in[18], (const float*)d_in[21]};
    const float* W1 = (const float*)d_in[22];
    const float* b1 = (const float*)d_in[23];
    const float* W2 = (const float*)d_in[24];
    const float* b2 = (const float*)d_in[25];
    const float* W3 = (const float*)d_in[26];
    const float* b3 = (const float*)d_in[27];
    const float* Wf = (const float*)d_in[28];
    const float* bf = (const float*)d_in[29];
    float* out = (float*)d_out;

    // ---- CSR build for all levels (concatenated) ----
    int nblk = (NTOT + 255) / 256;
    int eblk = (ETOT + 255) / 256;
    int sblk = (NTOT + 1023) / 1024;   // 586
    init_kernel<<<nblk, 256>>>(Wcl, Wcr, bc);
    count_all_kernel<<<eblk, 256>>>(edges[0], edges[1], edges[2],
                                    edges[3], edges[4], edges[5]);
    scan1_kernel<<<sblk, 256>>>();
    scan2_kernel<<<1, 1024>>>(sblk);
    scan3_kernel<<<nblk, 256>>>();
    fill_all_kernel<<<eblk, 256>>>(edges[0], edges[1], edges[2],
                                   edges[3], edges[4], edges[5],
                                   inv[0], inv[1], inv[2],
                                   inv[3], inv[4], inv[5]);

    // ---- levels coarse -> fine: fused conv, 4 nodes/warp, persistent grid --
    const int PERSIST = 4 * 148;   // 4 blocks/SM resident (launch_bounds 128,4)
    for (int l = 5; l >= 0; l--) {
        int n = LS[l];
        int warps  = (n + 3) / 4;
        int blocks = imax(1, imin((warps + 3) / 4, PERSIST));
        // conv1: bufA (prev level, via pre-mapped .y) -> bufB
        sage_conv_kernel<0, 1, 1, 0><<<blocks, 128>>>(inv[l], n, NOFF[l],
                                                      Wp_l[0], Wp_r[0], bp[0]);
        // conv2: bufB -> bufA (level 0: stream output, next reader is the MLP)
        if (l == 0)
            sage_conv_kernel<1, 0, 0, 1><<<blocks, 128>>>(inv[l], n, NOFF[l],
                                                          Wp_l[1], Wp_r[1], bp[1]);
        else
            sage_conv_kernel<1, 0, 0, 0><<<blocks, 128>>>(inv[l], n, NOFF[l],
                                                          Wp_l[1], Wp_r[1], bp[1]);
    }

    int n0 = NL0;
    mlp_kernel<<<2 * 148, 256>>>(n0, W1, b1, W2, b2, W3, b3, Wf, bf);

    qr_scalars_kernel<<<1, 1>>>();
    qr_finalize_kernel<<<2048, 256>>>(out, n0);
}

// round 16
// speedup vs baseline: 1.0352x; 1.0352x over previous
#include <cuda_runtime.h>
#include <math.h>

// ---------------------------------------------------------------------------
// ModelSpectral: hierarchical GraphSAGE + MLP + n x 2 Householder QR
// R13: conv weights moved from 64 persistent registers to PADDED-TRANSPOSED
//      smem (conflict-free float4 reads, reloaded per 4-node batch into the
//      gather's dead register slots). Register pressure ~128 -> ~75 =>
//      launch_bounds(128,7): 28 warps/SM vs 16. Instruction count ~same.
//      Everything else identical to the 853us R12 kernel.
// ---------------------------------------------------------------------------

#define NL0 524288
#define NL1 65536
#define NL2 8192
#define NL3 1024
#define NL4 128
#define NL5 16

#define NOFF0 0
#define NOFF1 524288
#define NOFF2 589824
#define NOFF3 598016
#define NOFF4 599040
#define NOFF5 599168
#define NTOT  599184

#define EL0 8388608
#define EL1 1048576
#define EL2 131072
#define EL3 16384
#define EL4 2048
#define EL5 256

#define EOFF0 0
#define EOFF1 8388608
#define EOFF2 9437184
#define EOFF3 9568256
#define EOFF4 9584640
#define EOFF5 9586688
#define ETOT  9586944

// scratch (device globals; no allocations allowed)
__device__ float  g_bufA[NL0 * 32];   // fp32 activations (conv1 in / conv2 out)
__device__ float  g_bufB[NL0 * 32];   // fp32 activations (conv1 out / conv2 in)
__device__ int    g_rowptr[NTOT + 1];
__device__ int2   g_colpair[ETOT];    // .x = raw src (conv2), .y = inv[src] (conv1)
__device__ int    g_cnt[NTOT];
__device__ int    g_partials[1024];
__device__ float  g_mat[NL0 * 2];
__device__ double g_red[3];
__device__ double g_scal[6];

// fast accurate-enough tanh: 1x EX2 + 1x fast div (~1e-7 abs err)
__device__ __forceinline__ float ftanh(float v) {
    float x = fminf(fmaxf(v, -15.f), 15.f);
    float e;
    asm("ex2.approx.f32 %0, %1;" : "=f"(e) : "f"(x * 2.8853900817779268f));
    return __fdividef(e - 1.f, e + 1.f);
}

// ---------------------------------------------------------------------------
// init: clear g_cnt everywhere; block 0 also computes the coarsest level
// (x = eye(2), coarse_edges = [[0,1],[1,0]] constant) and zeroes QR sums.
// ---------------------------------------------------------------------------
__global__ void init_kernel(const float* __restrict__ Wcl,
                            const float* __restrict__ Wcr,
                            const float* __restrict__ bc) {
    int i = blockIdx.x * blockDim.x + threadIdx.x;
    if (i < NTOT) g_cnt[i] = 0;
    if (blockIdx.x == 0) {
        int t = threadIdx.x;
        if (t < 64) {
            int r = t >> 5, c = t & 31;
            g_bufA[t] = ftanh(Wcl[(1 - r) * 32 + c] + Wcr[r * 32 + c] + bc[c]);
        }
        if (t < 3) g_red[t] = 0.0;
    }
}

// ---------------------------------------------------------------------------
// CSR build (by destination), ALL levels concatenated
// ---------------------------------------------------------------------------
__global__ void count_all_kernel(const int* __restrict__ e0, const int* __restrict__ e1,
                                 const int* __restrict__ e2, const int* __restrict__ e3,
                                 const int* __restrict__ e4, const int* __restrict__ e5) {
    int t = blockIdx.x * blockDim.x + threadIdx.x;
    int d;
    if      (t < EOFF1) d = NOFF0 + e0[EL0 + t];
    else if (t < EOFF2) d = NOFF1 + e1[EL1 + (t - EOFF1)];
    else if (t < EOFF3) d = NOFF2 + e2[EL2 + (t - EOFF2)];
    else if (t < EOFF4) d = NOFF3 + e3[EL3 + (t - EOFF3)];
    else if (t < EOFF5) d = NOFF4 + e4[EL4 + (t - EOFF4)];
    else if (t < ETOT)  d = NOFF5 + e5[EL5 + (t - EOFF5)];
    else return;
    atomicAdd(&g_cnt[d], 1);
}

// block-local exclusive scan (1024 items / block), block sums -> g_partials
__global__ void scan1_kernel() {
    __shared__ int sm[256];
    int t = threadIdx.x;
    int base = blockIdx.x * 1024 + t * 4;
    int v[4];
#pragma unroll
    for (int i = 0; i < 4; i++) v[i] = (base + i < NTOT) ? g_cnt[base + i] : 0;
    int s = v[0] + v[1] + v[2] + v[3];
    sm[t] = s;
    __syncthreads();
    for (int off = 1; off < 256; off <<= 1) {
        int y = (t >= off) ? sm[t - off] : 0;
        __syncthreads();
        sm[t] += y;
        __syncthreads();
    }
    int incl = sm[t];
    if (t == 255) g_partials[blockIdx.x] = incl;
    int run = incl - s;
#pragma unroll
    for (int i = 0; i < 4; i++) {
        if (base + i < NTOT) g_rowptr[base + i] = run;
        run += v[i];
    }
}

// exclusive scan of block partials (nb <= 1024), single block
__global__ void scan2_kernel(int nb) {
    __shared__ int sm[1024];
    int t = threadIdx.x;
    int v = (t < nb) ? g_partials[t] : 0;
    sm[t] = v;
    __syncthreads();
    for (int off = 1; off < 1024; off <<= 1) {
        int y = (t >= off) ? sm[t - off] : 0;
        __syncthreads();
        sm[t] += y;
        __syncthreads();
    }
    if (t < nb) g_partials[t] = sm[t] - v;
}

// add partials, clear cnt for the fill cursor, seal rowptr
__global__ void scan3_kernel() {
    int i = blockIdx.x * blockDim.x + threadIdx.x;
    if (i < NTOT) {
        g_rowptr[i] += g_partials[i >> 10];
        g_cnt[i] = 0;
    }
    if (i == 0) g_rowptr[NTOT] = ETOT;
}

// fill: one packed int2 write per edge (raw src + inv-mapped src)
__global__ void fill_all_kernel(const int* __restrict__ e0, const int* __restrict__ e1,
                                const int* __restrict__ e2, const int* __restrict__ e3,
                                const int* __restrict__ e4, const int* __restrict__ e5,
                                const int* __restrict__ i0, const int* __restrict__ i1,
                                const int* __restrict__ i2, const int* __restrict__ i3,
                                const int* __restrict__ i4, const int* __restrict__ i5) {
    int t = blockIdx.x * blockDim.x + threadIdx.x;
    int s, d, m;
    if      (t < EOFF1) { s = e0[t];         d = NOFF0 + e0[EL0 + t]; m = __ldg(&i0[s]); }
    else if (t < EOFF2) { int u = t - EOFF1; s = e1[u]; d = NOFF1 + e1[EL1 + u]; m = __ldg(&i1[s]); }
    else if (t < EOFF3) { int u = t - EOFF2; s = e2[u]; d = NOFF2 + e2[EL2 + u]; m = __ldg(&i2[s]); }
    else if (t < EOFF4) { int u = t - EOFF3; s = e3[u]; d = NOFF3 + e3[EL3 + u]; m = __ldg(&i3[s]); }
    else if (t < EOFF5) { int u = t - EOFF4; s = e4[u]; d = NOFF4 + e4[EL4 + u]; m = __ldg(&i4[s]); }
    else if (t < ETOT)  { int u = t - EOFF5; s = e5[u]; d = NOFF5 + e5[EL5 + u]; m = __ldg(&i5[s]); }
    else return;
    int p = g_rowptr[d] + atomicAdd(&g_cnt[d], 1);
    g_colpair[p] = make_int2(s, m);
}

// ---------------------------------------------------------------------------
// fused SAGEConv: y = tanh(mean_agg(x) @ Wl + x @ Wr + b)
// QUARTER-warp node assignment (4 chains/warp); lane = feature quad
// (float4, one warp LDG.128 = 4 neighbor rows). Neighbor indices hoisted
// 16-ahead. Weights live in PADDED-TRANSPOSED smem (row stride 36 floats =
// 144B: each 8-lane LDS.128 phase covers all 32 banks, conflict-free) and
// are reloaded per 4-node batch into transient registers.
// ---------------------------------------------------------------------------
template <int XSEL, int MAPPED, int SELF_INDIRECT, int STREAM_OUT>
__global__ __launch_bounds__(128, 7)
void sage_conv_kernel(const int* __restrict__ inv,
                      int n, int noff,
                      const float* __restrict__ Wl,
                      const float* __restrict__ Wr,
                      const float* __restrict__ b) {
    const float* __restrict__ x = XSEL ? g_bufB : g_bufA;
    float*       __restrict__ y = XSEL ? g_bufA : g_bufB;

    int lane = threadIdx.x & 31;
    int qtr  = lane >> 3;          // which node of the 4 (0..3)
    int sp   = lane & 7;           // feature-quad index (features 4sp..4sp+3)
    int wloc = threadIdx.x >> 5;   // 4 warps per block
    int gwarp   = (blockIdx.x * blockDim.x + threadIdx.x) >> 5;
    int totwarp = (gridDim.x * blockDim.x) >> 5;

    // transposed, padded weight tiles: sW?T[lane*36 + k] = W?[k*32 + lane]
    __shared__ __align__(16) float sWlT[32 * 36];
    __shared__ __align__(16) float sWrT[32 * 36];
    __shared__ float sB[32];
    for (int idx = threadIdx.x; idx < 1024; idx += 128) {
        int k = idx >> 5, l = idx & 31;
        sWlT[l * 36 + k] = Wl[idx];
        sWrT[l * 36 + k] = Wr[idx];
    }
    if (threadIdx.x < 32) sB[threadIdx.x] = b[threadIdx.x];
    __syncthreads();

    const float4* wl4 = (const float4*)sWlT + lane * 9;  // quads q=0..7 (9th = pad)
    const float4* wr4 = (const float4*)sWrT + lane * 9;
    float bj = sB[lane];

    __shared__ float sm[4][4][64];   // [warp][node][agg32|self32]

    for (int base = gwarp * 4; base < n; base += totwarp * 4) {
        int node = base + qtr;
        bool valid = node < n;

        int r0 = 0, r1 = 0;
        if (valid) {
            r0 = __ldg(&g_rowptr[noff + node]);
            r1 = __ldg(&g_rowptr[noff + node + 1]);
        }
        int deg = r1 - r0;

        float ax = 0.f, ay = 0.f, az = 0.f, aw = 0.f;
        for (int bs = r0; bs < r1; bs += 16) {
            // hoist 16 neighbor indices (covers the avg-16 degree in one shot)
            int c[16];
#pragma unroll
            for (int i = 0; i < 16; i++) {
                int idx = bs + i;
                if (idx < r1) {
                    int2 cp = __ldcs(&g_colpair[idx]);
                    c[i] = MAPPED ? cp.y : cp.x;
                } else {
                    c[i] = -1;
                }
            }
#pragma unroll
            for (int ph = 0; ph < 2; ph++) {
                float4 f[8];
#pragma unroll
                for (int i = 0; i < 8; i++) {
                    int cc = c[ph * 8 + i];
                    if (cc >= 0)
                        f[i] = __ldg((const float4*)(x + (cc << 5) + 4 * sp));
                    else
                        f[i] = make_float4(0.f, 0.f, 0.f, 0.f);
                }
                // tree sum of 8 float4s
#pragma unroll
                for (int st = 4; st >= 1; st >>= 1) {
#pragma unroll
                    for (int i = 0; i < st; i++) {
                        f[i].x += f[i + st].x;
                        f[i].y += f[i + st].y;
                        f[i].z += f[i + st].z;
                        f[i].w += f[i + st].w;
                    }
                }
                ax += f[0].x; ay += f[0].y; az += f[0].z; aw += f[0].w;
            }
        }
        float s = 1.0f / (float)(deg > 0 ? deg : 1);
        ax *= s; ay *= s; az *= s; aw *= s;

        float4 sf = make_float4(0.f, 0.f, 0.f, 0.f);
        if (valid) {
            int selfrow = SELF_INDIRECT ? __ldg(&inv[node]) : node;
            sf = __ldg((const float4*)(x + (selfrow << 5) + 4 * sp));
        }

        *((float4*)&sm[wloc][qtr][4 * sp])      = make_float4(ax, ay, az, aw);
        *((float4*)&sm[wloc][qtr][32 + 4 * sp]) = sf;
        __syncwarp();

        float acc[4];
#pragma unroll
        for (int h = 0; h < 4; h++) acc[h] = bj;

        {   // agg @ Wl — weight quads loaded once, serve all 4 nodes
            float4 wq[8];
#pragma unroll
            for (int q = 0; q < 8; q++) wq[q] = wl4[q];
#pragma unroll
            for (int h = 0; h < 4; h++) {
                const float4* s4 = (const float4*)sm[wloc][h];
#pragma unroll
                for (int q = 0; q < 8; q++) {
                    float4 va = s4[q];
                    acc[h] = fmaf(va.x, wq[q].x, acc[h]);
                    acc[h] = fmaf(va.y, wq[q].y, acc[h]);
                    acc[h] = fmaf(va.z, wq[q].z, acc[h]);
                    acc[h] = fmaf(va.w, wq[q].w, acc[h]);
                }
            }
        }
        {   // self @ Wr
            float4 wq[8];
#pragma unroll
            for (int q = 0; q < 8; q++) wq[q] = wr4[q];
#pragma unroll
            for (int h = 0; h < 4; h++) {
                const float4* s4 = (const float4*)sm[wloc][h] + 8;
#pragma unroll
                for (int q = 0; q < 8; q++) {
                    float4 vs = s4[q];
                    acc[h] = fmaf(vs.x, wq[q].x, acc[h]);
                    acc[h] = fmaf(vs.y, wq[q].y, acc[h]);
                    acc[h] = fmaf(vs.z, wq[q].z, acc[h]);
                    acc[h] = fmaf(vs.w, wq[q].w, acc[h]);
                }
            }
        }

#pragma unroll
        for (int h = 0; h < 4; h++) {
            int onode = base + h;
            if (onode < n) {
                float r = ftanh(acc[h]);
                if (STREAM_OUT) __stcs(&y[(onode << 5) + lane], r);
                else            y[(onode << 5) + lane] = r;
            }
        }
        __syncwarp();
    }
}

// ---------------------------------------------------------------------------
// MLP tail: 32 -> 16 -> 32 -> 32 -> 2 (tanh on first three), reads bufA
// (streaming), writes g_mat and accumulates the QR Gram sums.
// k-major loops with float4 weight loads (LDS.128: 4 weights/instruction).
// ---------------------------------------------------------------------------
__global__ void mlp_kernel(int n,
                           const float* __restrict__ W1, const float* __restrict__ b1,
                           const float* __restrict__ W2, const float* __restrict__ b2,
                           const float* __restrict__ W3, const float* __restrict__ b3,
                           const float* __restrict__ Wf, const float* __restrict__ bf) {
    __shared__ __align__(16) float sW1[512], sW2[512], sW3[1024], sWf[64];
    __shared__ float sb1[16], sb2[32], sb3[32], sbf[2];
    __shared__ double smr[3][8];
    int t = threadIdx.x;
    for (int i = t; i < 512; i += blockDim.x)  sW1[i] = W1[i];
    for (int i = t; i < 512; i += blockDim.x)  sW2[i] = W2[i];
    for (int i = t; i < 1024; i += blockDim.x) sW3[i] = W3[i];
    for (int i = t; i < 64; i += blockDim.x)   sWf[i] = Wf[i];
    if (t < 16) sb1[t] = b1[t];
    if (t < 32) sb2[t] = b2[t];
    if (t < 32) sb3[t] = b3[t];
    if (t < 2)  sbf[t] = bf[t];
    __syncthreads();

    const float4* sW1v = (const float4*)sW1;   // [32][4]
    const float4* sW2v = (const float4*)sW2;   // [16][8]
    const float4* sW3v = (const float4*)sW3;   // [32][8]
    const float2* sWfv = (const float2*)sWf;   // [32]

    double s11 = 0.0, s12 = 0.0, s22 = 0.0;

    for (int i = blockIdx.x * blockDim.x + t; i < n;
         i += gridDim.x * blockDim.x) {
        float h[32];
        const float4* xr = (const float4*)(g_bufA + i * 32);
#pragma unroll
        for (int q = 0; q < 8; q++) {
            float4 v = __ldcs(&xr[q]);
            h[q * 4] = v.x; h[q * 4 + 1] = v.y;
            h[q * 4 + 2] = v.z; h[q * 4 + 3] = v.w;
        }

        // layer 1: 32 -> 16
        float a1[16];
#pragma unroll
        for (int j = 0; j < 16; j++) a1[j] = sb1[j];
#pragma unroll
        for (int k = 0; k < 32; k++) {
            float hk = h[k];
#pragma unroll
            for (int j4 = 0; j4 < 4; j4++) {
                float4 w = sW1v[k * 4 + j4];
                a1[j4 * 4 + 0] = fmaf(hk, w.x, a1[j4 * 4 + 0]);
                a1[j4 * 4 + 1] = fmaf(hk, w.y, a1[j4 * 4 + 1]);
                a1[j4 * 4 + 2] = fmaf(hk, w.z, a1[j4 * 4 + 2]);
                a1[j4 * 4 + 3] = fmaf(hk, w.w, a1[j4 * 4 + 3]);
            }
        }
        float t1[16];
#pragma unroll
        for (int j = 0; j < 16; j++) t1[j] = ftanh(a1[j]);

        // layer 2: 16 -> 32
        float a2[32];
#pragma unroll
        for (int j = 0; j < 32; j++) a2[j] = sb2[j];
#pragma unroll
        for (int k = 0; k < 16; k++) {
            float hk = t1[k];
#pragma unroll
            for (int j4 = 0; j4 < 8; j4++) {
                float4 w = sW2v[k * 8 + j4];
                a2[j4 * 4 + 0] = fmaf(hk, w.x, a2[j4 * 4 + 0]);
                a2[j4 * 4 + 1] = fmaf(hk, w.y, a2[j4 * 4 + 1]);
                a2[j4 * 4 + 2] = fmaf(hk, w.z, a2[j4 * 4 + 2]);
                a2[j4 * 4 + 3] = fmaf(hk, w.w, a2[j4 * 4 + 3]);
            }
        }
        float t2[32];
#pragma unroll
        for (int j = 0; j < 32; j++) t2[j] = ftanh(a2[j]);

        // layer 3: 32 -> 32
        float a3[32];
#pragma unroll
        for (int j = 0; j < 32; j++) a3[j] = sb3[j];
#pragma unroll
        for (int k = 0; k < 32; k++) {
            float hk = t2[k];
#pragma unroll
            for (int j4 = 0; j4 < 8; j4++) {
                float4 w = sW3v[k * 8 + j4];
                a3[j4 * 4 + 0] = fmaf(hk, w.x, a3[j4 * 4 + 0]);
                a3[j4 * 4 + 1] = fmaf(hk, w.y, a3[j4 * 4 + 1]);
                a3[j4 * 4 + 2] = fmaf(hk, w.z, a3[j4 * 4 + 2]);
                a3[j4 * 4 + 3] = fmaf(hk, w.w, a3[j4 * 4 + 3]);
            }
        }

        // final: 32 -> 2
        float o0 = sbf[0], o1 = sbf[1];
#pragma unroll
        for (int k = 0; k < 32; k++) {
            float hk = ftanh(a3[k]);
            float2 w = sWfv[k];
            o0 = fmaf(hk, w.x, o0);
            o1 = fmaf(hk, w.y, o1);
        }

        g_mat[i * 2]     = o0;
        g_mat[i * 2 + 1] = o1;
        s11 += (double)o0 * o0;
        s12 += (double)o0 * o1;
        s22 += (double)o1 * o1;
    }

    // block reduction of Gram sums
#pragma unroll
    for (int off = 16; off; off >>= 1) {
        s11 += __shfl_down_sync(0xffffffffu, s11, off);
        s12 += __shfl_down_sync(0xffffffffu, s12, off);
        s22 += __shfl_down_sync(0xffffffffu, s22, off);
    }
    int lane = t & 31, w = t >> 5;
    if (lane == 0) { smr[0][w] = s11; smr[1][w] = s12; smr[2][w] = s22; }
    __syncthreads();
    if (t == 0) {
        double a = 0, bb = 0, c = 0;
        int nw = blockDim.x >> 5;
        for (int i = 0; i < nw; i++) { a += smr[0][i]; bb += smr[1][i]; c += smr[2][i]; }
        atomicAdd(&g_red[0], a);
        atomicAdd(&g_red[1], bb);
        atomicAdd(&g_red[2], c);
    }
}

// ---------------------------------------------------------------------------
// QR (n x 2) via LAPACK-convention Householder reflections
// ---------------------------------------------------------------------------
__global__ void qr_scalars_kernel() {
    double s11 = g_red[0], s12 = g_red[1], s22 = g_red[2];
    double a10 = g_mat[0], a20 = g_mat[1];
    double a11 = g_mat[2], a21 = g_mat[3];
    double nrm1   = sqrt(s11);
    double beta1  = -copysign(nrm1, a10);
    double denom1 = a10 - beta1;
    double tau1   = (beta1 - a10) / beta1;
    double gg     = a20 + (s12 - a10 * a20) / denom1;   // v1^T a2
    double c20    = a20 - tau1 * gg;                    // (H1 a2)[0] = r12
    double v11    = a11 / denom1;
    double c21    = a21 - tau1 * v11 * gg;              // (H1 a2)[1]
    double n2sq   = s22 - c20 * c20;
    if (n2sq < 0) n2sq = 0;
    double nrm2   = sqrt(n2sq);
    double beta2  = -copysign(nrm2, c21);
    double denom2 = c21 - beta2;
    double tau2   = (beta2 - c21) / beta2;
    double v1v2 = v11 + (-gg - c20 - v11 * c21) / denom2;
    double w    = v11 - tau2 * v1v2;
    g_scal[0] = tau1;  g_scal[1] = 1.0 / denom1; g_scal[2] = gg;
    g_scal[3] = tau2;  g_scal[4] = 1.0 / denom2; g_scal[5] = w;
}

__global__ void qr_finalize_kernel(float* __restrict__ out, int n) {
    float tau1 = (float)g_scal[0], id1 = (float)g_scal[1], gg = (float)g_scal[2];
    float tau2 = (float)g_scal[3], id2 = (float)g_scal[4], w  = (float)g_scal[5];
    for (int j = blockIdx.x * blockDim.x + threadIdx.x; j < n;
         j += gridDim.x * blockDim.x) {
        float a1j = g_mat[2 * j], a2j = g_mat[2 * j + 1];
        float v1 = (j == 0) ? 1.f : a1j * id1;
        float c2 = a2j - tau1 * v1 * gg;
        float v2 = (j == 0) ? 0.f : ((j == 1) ? 1.f : c2 * id2);
        float q0 = -tau1 * v1;
        if (j == 0) q0 += 1.f;
        float q1 = -tau2 * v2 - tau1 * v1 * w;
        if (j == 1) q1 += 1.f;
        out[2 * j]     = q0;
        out[2 * j + 1] = q1;
    }
}

// ---------------------------------------------------------------------------
static inline int imin(int a, int b) { return a < b ? a : b; }
static inline int imax(int a, int b) { return a > b ? a : b; }

extern "C" void kernel_launch(void* const* d_in, const int* in_sizes, int n_in,
                              void* d_out, int out_size) {
    (void)in_sizes; (void)n_in; (void)out_size;
    static const int LS[6]   = {NL0, NL1, NL2, NL3, NL4, NL5};
    static const int NOFF[6] = {NOFF0, NOFF1, NOFF2, NOFF3, NOFF4, NOFF5};

    const int* edges[6];
    const int* inv[6];
    for (int l = 0; l < 6; l++) {
        edges[l] = (const int*)d_in[2 * l];
        inv[l]   = (const int*)d_in[2 * l + 1];
    }
    const float* Wcl = (const float*)d_in[13];
    const float* Wcr = (const float*)d_in[14];
    const float* bc  = (const float*)d_in[15];
    const float* Wp_l[2] = {(const float*)d_in[16], (const float*)d_in[19]};
    const float* Wp_r[2] = {(const float*)d_in[17], (const float*)d_in[20]};
    const float* bp[2]   = {(const float*)d_in[18], (const float*)d_in[21]};
    const float* W1 = (const float*)d_in[22];
    const float* b1 = (const float*)d_in[23];
    const float* W2 = (const float*)d_in[24];
    const float* b2 = (const float*)d_in[25];
    const float* W3 = (const float*)d_in[26];
    const float* b3 = (const float*)d_in[27];
    const float* Wf = (const float*)d_in[28];
    const float* bf = (const float*)d_in[29];
    float* out = (float*)d_out;

    // ---- CSR build for all levels (concatenated) ----
    int nblk = (NTOT + 255) / 256;
    int eblk = (ETOT + 255) / 256;
    int sblk = (NTOT + 1023) / 1024;   // 586
    init_kernel<<<nblk, 256>>>(Wcl, Wcr, bc);
    count_all_kernel<<<eblk, 256>>>(edges[0], edges[1], edges[2],
                                    edges[3], edges[4], edges[5]);
    scan1_kernel<<<sblk, 256>>>();
    scan2_kernel<<<1, 1024>>>(sblk);
    scan3_kernel<<<nblk, 256>>>();
    fill_all_kernel<<<eblk, 256>>>(edges[0], edges[1], edges[2],
                                   edges[3], edges[4], edges[5],
                                   inv[0], inv[1], inv[2],
                                   inv[3], inv[4], inv[5]);

    // ---- levels coarse -> fine: fused conv, 4 nodes/warp, persistent grid --
    const int PERSIST = 7 * 148;   // 7 blocks/SM resident (launch_bounds 128,7)
    for (int l = 5; l >= 0; l--) {
        int n = LS[l];
        int warps  = (n + 3) / 4;
        int blocks = imax(1, imin((warps + 3) / 4, PERSIST));
        // conv1: bufA (prev level, via pre-mapped .y) -> bufB
        sage_conv_kernel<0, 1, 1, 0><<<blocks, 128>>>(inv[l], n, NOFF[l],
                                                      Wp_l[0], Wp_r[0], bp[0]);
        // conv2: bufB -> bufA (level 0: stream output, next reader is the MLP)
        if (l == 0)
            sage_conv_kernel<1, 0, 0, 1><<<blocks, 128>>>(inv[l], n, NOFF[l],
                                                          Wp_l[1], Wp_r[1], bp[1]);
        else
            sage_conv_kernel<1, 0, 0, 0><<<blocks, 128>>>(inv[l], n, NOFF[l],
                                                          Wp_l[1], Wp_r[1], bp[1]);
    }

    int n0 = NL0;
    mlp_kernel<<<2 * 148, 256>>>(n0, W1, b1, W2, b2, W3, b3, Wf, bf);

    qr_scalars_kernel<<<1, 1>>>();
    qr_finalize_kernel<<<2048, 256>>>(out, n0);
}